// round 13
// baseline (speedup 1.0000x reference)
#include <cuda_runtime.h>
#include <cstdint>

// Volume: 256^3 voxels. Inputs (metadata order):
//   d_in[0] vessel_labels  int32   [16777216]
//   d_in[1] id_intensity   float32 [256]
//   d_in[2] id_is_dark     int32   [256]
//   d_in[3] parenchyma     float32 [16777216]
// Output (float32, 67108864): out [16.78M] then onehot [3,16.78M]
//   ch0 = background, ch1 = dark vessel, ch2 = bright vessel.
//
// FINAL (12-round session): hard HBM-bound — 128 MB reads + 256 MB writes
// irreducible; plateau at ~5.8 TB/s counter-level for this 1:2 R:W mix.
// Best config, reproduced twice at ncu 59.17 us / DRAM 73.4-73.5%:
//   TPB=256, 2 vec4 tiles/thread, __ldcs streaming loads (MLP=4,
//   front-batched), per-stream grouped __stcs stores (1KB contiguous
//   warp burst per output stream), 32 regs, occ ~86-90%.
// Axes closed: TPB{128,256,512}, ITEMS{1,2,4}, vec{4,8}, store{.cs,.wb,.wt},
// persistent grid, software pipelining, store grouping (the one real win).

#define N_VOX (256u * 256u * 256u)
#define VEC   (N_VOX / 4u)             // 4,194,304 vec4 elements
#define TPB   256u
#define ITEMS 2u                       // vec4 tiles per thread
#define BLOCKS (VEC / (TPB * ITEMS))   // 8192

__global__ __launch_bounds__(TPB, 8)
void yibei_kernel(const int4* __restrict__ labels4,
                  const float4* __restrict__ par4,
                  const float* __restrict__ id_intensity,
                  const int* __restrict__ id_is_dark,
                  float* __restrict__ out)
{
    // Fused LUT in shared: .x = intensity bits (id 0 forced to 1.0f), .y = dark flag
    __shared__ uint2 s_lut[256];
    {
        int t = threadIdx.x;   // blockDim.x == 256
        float inten = (t == 0) ? 1.0f : __ldg(&id_intensity[t]);
        s_lut[t] = make_uint2(__float_as_uint(inten), (unsigned)__ldg(&id_is_dark[t]));
    }
    __syncthreads();

    // Two contiguous-per-warp tiles, TPB apart: all accesses 128B-coalesced,
    // and per-stream store pairs form 1KB-contiguous warp bursts.
    unsigned base = blockIdx.x * (TPB * ITEMS) + threadIdx.x;
    unsigned i0 = base;
    unsigned i1 = base + TPB;

    // Front-batch all global loads (MLP = 4), streaming policy.
    int4   lab0 = __ldcs(&labels4[i0]);
    int4   lab1 = __ldcs(&labels4[i1]);
    float4 p0   = __ldcs(&par4[i0]);
    float4 p1   = __ldcs(&par4[i1]);

    // Per-lane classification, kept in registers after unroll.
    float s0[4], s1[4];
    bool  m0[4], m1[4], d0[4], d1[4];
    #pragma unroll
    for (int k = 0; k < 4; ++k) {
        int l0 = (&lab0.x)[k];
        int l1 = (&lab1.x)[k];
        uint2 e0 = s_lut[l0];
        uint2 e1 = s_lut[l1];
        s0[k] = __uint_as_float(e0.x);   // lut[0] == 1.0 -> branch-free scale
        s1[k] = __uint_as_float(e1.x);
        m0[k] = (l0 != 0);               m1[k] = (l1 != 0);
        d0[k] = m0[k] & (e0.y == 1u);    d1[k] = m1[k] & (e1.y == 1u);
    }

    float4* o4 = (float4*)out;
    float4 a, b;

    // Stream 0: scaled parenchyma (grouped: both tiles back-to-back)
    #pragma unroll
    for (int k = 0; k < 4; ++k) { (&a.x)[k] = (&p0.x)[k] * s0[k];
                                  (&b.x)[k] = (&p1.x)[k] * s1[k]; }
    __stcs(&o4[i0], a);
    __stcs(&o4[i1], b);

    // Stream 1: background channel
    #pragma unroll
    for (int k = 0; k < 4; ++k) { (&a.x)[k] = m0[k] ? 0.0f : 1.0f;
                                  (&b.x)[k] = m1[k] ? 0.0f : 1.0f; }
    __stcs(&o4[VEC + i0], a);
    __stcs(&o4[VEC + i1], b);

    // Stream 2: dark-vessel channel
    #pragma unroll
    for (int k = 0; k < 4; ++k) { (&a.x)[k] = d0[k] ? 1.0f : 0.0f;
                                  (&b.x)[k] = d1[k] ? 1.0f : 0.0f; }
    __stcs(&o4[2u * VEC + i0], a);
    __stcs(&o4[2u * VEC + i1], b);

    // Stream 3: bright-vessel channel
    #pragma unroll
    for (int k = 0; k < 4; ++k) { (&a.x)[k] = (m0[k] & !d0[k]) ? 1.0f : 0.0f;
                                  (&b.x)[k] = (m1[k] & !d1[k]) ? 1.0f : 0.0f; }
    __stcs(&o4[3u * VEC + i0], a);
    __stcs(&o4[3u * VEC + i1], b);
}

extern "C" void kernel_launch(void* const* d_in, const int* in_sizes, int n_in,
                              void* d_out, int out_size)
{
    const int4*   labels4 = (const int4*)d_in[0];
    const float*  id_int  = (const float*)d_in[1];
    const int*    id_dark = (const int*)d_in[2];
    const float4* par4    = (const float4*)d_in[3];
    float*        out     = (float*)d_out;

    yibei_kernel<<<BLOCKS, TPB>>>(labels4, par4, id_int, id_dark, out);
}

// round 14
// speedup vs baseline: 1.0195x; 1.0195x over previous
#include <cuda_runtime.h>
#include <cstdint>

// Volume: 256^3 voxels. R14 probe: TMA bulk stores.
// Stage each CTA's outputs in SMEM, then issue 4 x 4KB cp.async.bulk
// shared->global stores (one per output stream) from a single thread.
// Hypothesis: multi-KB single-op bursts improve DRAM write page locality
// vs interleaved 128B STG wavefronts.
//
// Inputs (metadata order):
//   d_in[0] vessel_labels  int32   [16777216]
//   d_in[1] id_intensity   float32 [256]
//   d_in[2] id_is_dark     int32   [256]
//   d_in[3] parenchyma     float32 [16777216]
// Output (float32, 67108864): out [16.78M] then onehot [3,16.78M].

#define N_VOX (256u * 256u * 256u)
#define VEC   (N_VOX / 4u)        // 4,194,304 vec4 elements
#define TPB   256u
#define BLOCKS (VEC / TPB)        // 16384 CTAs, 1 vec4/thread
#define CHUNK_BYTES (TPB * 16u)   // 4096 B per output stream per CTA

__device__ __forceinline__ unsigned smem_u32(const void* p) {
    return (unsigned)__cvta_generic_to_shared(p);
}

__global__ __launch_bounds__(TPB, 8)
void yibei_kernel(const int4* __restrict__ labels4,
                  const float4* __restrict__ par4,
                  const float* __restrict__ id_intensity,
                  const int* __restrict__ id_is_dark,
                  float* __restrict__ out)
{
    // Fused LUT: .x = intensity bits (id 0 forced to 1.0f), .y = dark flag
    __shared__ uint2 s_lut[256];
    // Staging buffers: 4 streams x 4KB, 16B-aligned for cp.async.bulk.
    __shared__ __align__(128) float4 s_buf[4][TPB];

    {
        int t = threadIdx.x;   // blockDim.x == 256
        float inten = (t == 0) ? 1.0f : __ldg(&id_intensity[t]);
        s_lut[t] = make_uint2(__float_as_uint(inten), (unsigned)__ldg(&id_is_dark[t]));
    }
    __syncthreads();

    unsigned i = blockIdx.x * TPB + threadIdx.x;   // vec4 index

    int4   lab = __ldcs(&labels4[i]);
    float4 p   = __ldcs(&par4[i]);

    float4 o, c0, c1, c2;
    #pragma unroll
    for (int k = 0; k < 4; ++k) {
        int   l  = (&lab.x)[k];
        float pv = (&p.x)[k];
        uint2 e  = s_lut[l];
        bool  m  = (l != 0);
        bool  d  = m & (e.y == 1u);
        (&o.x)[k]  = pv * __uint_as_float(e.x);   // lut[0] == 1.0 -> branch-free
        (&c0.x)[k] = m ? 0.0f : 1.0f;
        (&c1.x)[k] = d ? 1.0f : 0.0f;
        (&c2.x)[k] = (m & !d) ? 1.0f : 0.0f;
    }

    int t = threadIdx.x;
    s_buf[0][t] = o;
    s_buf[1][t] = c0;
    s_buf[2][t] = c1;
    s_buf[3][t] = c2;
    __syncthreads();

    if (t == 0) {
        // Make generic-proxy SMEM writes visible to the async (TMA) proxy.
        asm volatile("fence.proxy.async.shared::cta;" ::: "memory");

        unsigned cta_base = blockIdx.x * TPB;          // vec4 offset of this CTA
        float4* o4 = (float4*)out;

        #pragma unroll
        for (int s = 0; s < 4; ++s) {
            void* dst = (void*)&o4[(size_t)s * VEC + cta_base];
            unsigned src = smem_u32(&s_buf[s][0]);
            asm volatile(
                "cp.async.bulk.global.shared::cta.bulk_group [%0], [%1], %2;"
                :: "l"(dst), "r"(src), "n"(CHUNK_BYTES)
                : "memory");
        }
        asm volatile("cp.async.bulk.commit_group;" ::: "memory");
        asm volatile("cp.async.bulk.wait_group 0;" ::: "memory");
    }
}

extern "C" void kernel_launch(void* const* d_in, const int* in_sizes, int n_in,
                              void* d_out, int out_size)
{
    const int4*   labels4 = (const int4*)d_in[0];
    const float*  id_int  = (const float*)d_in[1];
    const int*    id_dark = (const int*)d_in[2];
    const float4* par4    = (const float4*)d_in[3];
    float*        out     = (float*)d_out;

    yibei_kernel<<<BLOCKS, TPB>>>(labels4, par4, id_int, id_dark, out);
}